// round 13
// baseline (speedup 1.0000x reference)
#include <cuda_runtime.h>
#include <cstdint>

#define B_   2
#define S_   2048
#define H_   16
#define KVH_ 8
#define D_   128
#define HID_ 2048
#define IN_  4096
#define M_   (B_*S_)

// ---------------- scratch (static device globals; no allocation) ----------------
__device__ float g_Q [(size_t)M_ * HID_];        // [tok][h*128+d]  (post-rope)
__device__ float g_K [(size_t)M_ * KVH_ * D_];   // [tok][kvh*128+d]
__device__ float g_V [(size_t)M_ * KVH_ * D_];
__device__ float g_AO[(size_t)M_ * HID_];        // attention output [b,s,h,d]

// ---------------- packed f32x2 helpers (attention) ----------------
__device__ __forceinline__ unsigned long long pk2(float lo, float hi) {
    unsigned long long r;
    asm("mov.b64 %0, {%1, %2};" : "=l"(r) : "f"(lo), "f"(hi));
    return r;
}
__device__ __forceinline__ void fma2(unsigned long long& c, unsigned long long a, unsigned long long b) {
    asm("fma.rn.f32x2 %0, %1, %2, %0;" : "+l"(c) : "l"(a), "l"(b));
}
__device__ __forceinline__ void mul2(unsigned long long& c, unsigned long long a) {
    asm("mul.rn.f32x2 %0, %0, %1;" : "+l"(c) : "l"(a));
}
__device__ __forceinline__ float2 upk2(unsigned long long v) {
    float2 f;
    asm("mov.b64 {%0, %1}, %2;" : "=f"(f.x), "=f"(f.y) : "l"(v));
    return f;
}

// ---------------- tf32 / ldmatrix helpers ----------------
__device__ __forceinline__ uint32_t f2tf(float x) {
    uint32_t r;
    asm("cvt.rna.tf32.f32 %0, %1;" : "=r"(r) : "f"(x));
    return r;
}
__device__ __forceinline__ uint32_t smem_u32(const void* p) {
    uint32_t a;
    asm("{ .reg .u64 t; cvta.to.shared.u64 t, %1; cvt.u32.u64 %0, t; }" : "=r"(a) : "l"(p));
    return a;
}
__device__ __forceinline__ void mma_tf32(float* d, const uint32_t* a, const uint32_t* b) {
    asm volatile("mma.sync.aligned.m16n8k8.row.col.f32.tf32.tf32.f32 "
        "{%0,%1,%2,%3}, {%4,%5,%6,%7}, {%8,%9}, {%0,%1,%2,%3};"
        : "+f"(d[0]), "+f"(d[1]), "+f"(d[2]), "+f"(d[3])
        : "r"(a[0]), "r"(a[1]), "r"(a[2]), "r"(a[3]), "r"(b[0]), "r"(b[1]));
}
__device__ __forceinline__ void ldsm_x4(uint32_t* r, uint32_t addr) {
    asm volatile("ldmatrix.sync.aligned.m8n8.x4.shared.b16 {%0,%1,%2,%3}, [%4];"
        : "=r"(r[0]), "=r"(r[1]), "=r"(r[2]), "=r"(r[3]) : "r"(addr));
}
__device__ __forceinline__ void ldsm_x2(uint32_t* r, uint32_t addr) {
    asm volatile("ldmatrix.sync.aligned.m8n8.x2.shared.b16 {%0,%1}, [%2];"
        : "=r"(r[0]), "=r"(r[1]) : "r"(addr));
}

// ---------------- tf32 tensor-core GEMM:  C[m][n] = sum_k A[m][k]*W[n][k] ----------------
// 128x128 block tile, BK=16, 256 threads (8 warps as 2m x 4n -> warp tile 64x32),
// mma.m16n8k8. Fragments loaded with ldmatrix: A = LDSM.x4 (one per m16k8 frag),
// B = LDSM.x2 (one per n8k8 frag). Smem row-major with pad 20 (80B row stride ->
// 8 ldmatrix row-pointers hit 8 distinct banks). Single buffer + register prefetch.
__device__ __forceinline__ void gemm_tf32_body(const float* __restrict__ A,
                                               const float* __restrict__ W,
                                               float* __restrict__ C,
                                               int Ndim, int Kdim, int m0, int n0)
{
    __shared__ uint32_t As[128][20];
    __shared__ uint32_t Ws[128][20];

    const int t    = threadIdx.x;
    const int warp = t >> 5, lane = t & 31;
    const int grp  = lane >> 2, tig = lane & 3;
    const int wm   = (warp >> 2) * 64;   // 0 / 64
    const int wn   = (warp & 3) * 32;    // 0..96

    // ldmatrix per-lane row pointers
    const int l8 = lane & 7, lq = lane >> 3;     // lq = matrix index 0..3
    const uint32_t sA = smem_u32(As);
    const uint32_t sW = smem_u32(Ws);
    // A frag (m16k8): block j: rows +8*(j&1), cols +4*(j>>1)
    const uint32_t aBase = sA + (uint32_t)(((wm + (lq & 1) * 8 + l8) * 20 + (lq >> 1) * 4) << 2);
    // B frag (n8k8): block j (x2 uses lanes 0-15): cols +4*(j&1)
    const uint32_t bBase = sW + (uint32_t)(((wn + l8) * 20 + (lq & 1) * 4) << 2);

    // loaders: 128 rows x 16 k = 512 float4 each; 2 rows per thread
    const int rowX = t >> 2;             // 0..63
    const int kc   = (t & 3) * 4;        // 0,4,8,12

    const float* Ap0 = A + (size_t)(m0 + rowX) * Kdim + kc;
    const float* Ap1 = A + (size_t)(m0 + rowX + 64) * Kdim + kc;
    const float* Wp0 = W + (size_t)(n0 + rowX) * Kdim + kc;
    const float* Wp1 = W + (size_t)(n0 + rowX + 64) * Kdim + kc;

    float acc[4][4][4];
#pragma unroll
    for (int i = 0; i < 4; i++)
#pragma unroll
        for (int j = 0; j < 4; j++)
#pragma unroll
            for (int r = 0; r < 4; r++) acc[i][j][r] = 0.f;

    float4 fa0 = *(const float4*)Ap0;
    float4 fa1 = *(const float4*)Ap1;
    float4 fb0 = *(const float4*)Wp0;
    float4 fb1 = *(const float4*)Wp1;

    const int KT = Kdim >> 4;
    for (int kt = 0; kt < KT; ++kt) {
        // stage current tile (rna->tf32), vectorized STS.128
        *(uint4*)&As[rowX][kc]       = make_uint4(f2tf(fa0.x), f2tf(fa0.y), f2tf(fa0.z), f2tf(fa0.w));
        *(uint4*)&As[rowX + 64][kc]  = make_uint4(f2tf(fa1.x), f2tf(fa1.y), f2tf(fa1.z), f2tf(fa1.w));
        *(uint4*)&Ws[rowX][kc]       = make_uint4(f2tf(fb0.x), f2tf(fb0.y), f2tf(fb0.z), f2tf(fb0.w));
        *(uint4*)&Ws[rowX + 64][kc]  = make_uint4(f2tf(fb1.x), f2tf(fb1.y), f2tf(fb1.z), f2tf(fb1.w));
        __syncthreads();

        // prefetch next k-tile into registers
        if (kt + 1 < KT) {
            const int off = (kt + 1) << 4;
            fa0 = *(const float4*)(Ap0 + off);
            fa1 = *(const float4*)(Ap1 + off);
            fb0 = *(const float4*)(Wp0 + off);
            fb1 = *(const float4*)(Wp1 + off);
        }

#pragma unroll
        for (int ks = 0; ks < 16; ks += 8) {
            uint32_t a[4][4], b[4][2];
#pragma unroll
            for (int mt = 0; mt < 4; mt++)
                ldsm_x4(a[mt], aBase + (uint32_t)((mt * 16 * 20 + ks) << 2));
#pragma unroll
            for (int nt = 0; nt < 4; nt++)
                ldsm_x2(b[nt], bBase + (uint32_t)((nt * 8 * 20 + ks) << 2));
#pragma unroll
            for (int mt = 0; mt < 4; mt++)
#pragma unroll
                for (int nt = 0; nt < 4; nt++)
                    mma_tf32(acc[mt][nt], a[mt], b[nt]);
        }
        __syncthreads();
    }

    // epilogue: c0,c1 -> (row, col..col+1); c2,c3 -> (row+8, ...)
#pragma unroll
    for (int mt = 0; mt < 4; mt++) {
        const int row = m0 + wm + mt * 16 + grp;
#pragma unroll
        for (int nt = 0; nt < 4; nt++) {
            const int col = n0 + wn + nt * 8 + tig * 2;
            *(float2*)(C + (size_t)row * Ndim + col)       = make_float2(acc[mt][nt][0], acc[mt][nt][1]);
            *(float2*)(C + (size_t)(row + 8) * Ndim + col) = make_float2(acc[mt][nt][2], acc[mt][nt][3]);
        }
    }
}

// fused QKV GEMM: n-blocks of 128 cover Wq (16), Wk (8), Wv (8)
__global__ __launch_bounds__(256, 2)
void qkv_gemm(const float* __restrict__ A,
              const float* __restrict__ Wq,
              const float* __restrict__ Wk,
              const float* __restrict__ Wv)
{
    const int nb = blockIdx.x;
    const int m0 = blockIdx.y << 7;
    const float* W;
    float* C;
    int Ndim, n0;
    if (nb < 16)      { W = Wq; C = g_Q; Ndim = HID_;       n0 = nb * 128; }
    else if (nb < 24) { W = Wk; C = g_K; Ndim = KVH_ * D_;  n0 = (nb - 16) * 128; }
    else              { W = Wv; C = g_V; Ndim = KVH_ * D_;  n0 = (nb - 24) * 128; }
    gemm_tf32_body(A, W, C, Ndim, IN_, m0, n0);
}

__global__ __launch_bounds__(256, 2)
void gemm_nt(const float* __restrict__ A, const float* __restrict__ W,
             float* __restrict__ C, int Ndim, int Kdim)
{
    gemm_tf32_body(A, W, C, Ndim, Kdim, blockIdx.y << 7, blockIdx.x << 7);
}

// ---------------- RoPE (in-place on g_Q, g_K) ----------------
__global__ void rope_kernel(const float* __restrict__ cosb, const float* __restrict__ sinb)
{
    const int idx  = blockIdx.x * 256 + threadIdx.x;
    const int d    = idx & 63;
    const int rest = idx >> 6;
    const int head = rest % 24;       // 0..15 -> Q heads, 16..23 -> K heads
    const int tok  = rest / 24;
    const float c1 = cosb[(size_t)tok * D_ + d];
    const float s1 = sinb[(size_t)tok * D_ + d];
    const float c2 = cosb[(size_t)tok * D_ + d + 64];
    const float s2 = sinb[(size_t)tok * D_ + d + 64];
    float* X = (head < 16) ? (g_Q + (size_t)tok * HID_ + head * D_)
                           : (g_K + (size_t)tok * (KVH_ * D_) + (head - 16) * D_);
    const float x1 = X[d], x2 = X[d + 64];
    X[d]      = x1 * c1 - x2 * s1;
    X[d + 64] = x2 * c2 + x1 * s2;
}

// ---------------- flash attention (fp32 FFMA2, unchanged) ----------------
#define QS_OFF 0
#define KS_OFF (64*132)
#define VS_OFF (2*64*132)
#define PS_OFF (3*64*132)
#define ES_OFF (PS_OFF + 64*68)
#define WS_OFF (ES_OFF + 192)
#define MS_OFF (WS_OFF + 192)
#define LS_OFF (MS_OFF + 64)
#define ATTN_SMEM_FLOATS (LS_OFF + 64)
#define ATTN_SMEM_BYTES  (ATTN_SMEM_FLOATS * 4)

__global__ __launch_bounds__(256)
void attn_kernel(const float* __restrict__ cK, const float* __restrict__ cV)
{
    extern __shared__ float sm[];
    float* Qs   = sm + QS_OFF;
    float* Ks   = sm + KS_OFF;
    float* Vs   = sm + VS_OFF;
    float* Ps   = sm + PS_OFF;
    float* es   = sm + ES_OFF;
    float* ws   = sm + WS_OFF;
    float* ms_s = sm + MS_OFF;
    float* ls_s = sm + LS_OFF;

    const int t  = threadIdx.x, tx = t & 15, ty = t >> 4;
    const int bh = blockIdx.x;
    const int qb = (int)gridDim.y - 1 - (int)blockIdx.y;
    const int b  = bh >> 4, h = bh & 15;
    const float scale = 0.08838834764831845f;

    const size_t q_row0 = ((size_t)(b * S_) + qb * 64) * HID_ + h * D_;
#pragma unroll
    for (int p = 0; p < 8; p++) {
        const int id = t + p * 256;
        const int row = id >> 5, c4 = (id & 31) * 4;
        *(float4*)&Qs[row * 132 + c4] = *(const float4*)(g_Q + q_row0 + (size_t)row * HID_ + c4);
    }
    __syncthreads();

    if (t < 192) {
        const int row = t & 63, l = t >> 6;
        const int qpos = qb * 64 + row;
        const float* ek;
        if (l == 2) ek = g_K + ((size_t)(b * S_ + qpos)) * (KVH_ * D_) + (h >> 1) * D_;
        else        ek = cK + (((size_t)((l + 1) * B_ + b) * H_ + h) * S_ + qpos) * D_;
        float acc = 0.f;
#pragma unroll 8
        for (int dd = 0; dd < 128; dd += 4) {
            float4 kv = *(const float4*)(ek + dd);
            float4 qv = *(const float4*)&Qs[row * 132 + dd];
            acc += qv.x * kv.x + qv.y * kv.y + qv.z * kv.z + qv.w * kv.w;
        }
        es[row * 3 + l] = acc * scale;
    }
    __syncthreads();
    if (t < 64) {
        const float e0 = es[t * 3], e1 = es[t * 3 + 1], e2 = es[t * 3 + 2];
        const float mm = fmaxf(e0, fmaxf(e1, e2));
        const float w0 = __expf(e0 - mm), w1 = __expf(e1 - mm), w2 = __expf(e2 - mm);
        ws[t * 3] = w0; ws[t * 3 + 1] = w1; ws[t * 3 + 2] = w2;
        ms_s[t] = mm; ls_s[t] = w0 + w1 + w2;
    }
    __syncthreads();

    float m_r[4], l_r[4];
    unsigned long long o2[4][4];
#pragma unroll
    for (int ri = 0; ri < 4; ri++) {
        const int row = ty + 16 * ri;
        const int qpos = qb * 64 + row;
        m_r[ri] = ms_s[row]; l_r[ri] = ls_s[row];
        const float* ev0 = cV + (((size_t)(1 * B_ + b) * H_ + h) * S_ + qpos) * D_ + tx * 8;
        const float* ev1 = cV + (((size_t)(2 * B_ + b) * H_ + h) * S_ + qpos) * D_ + tx * 8;
        const float* ev2 = g_V + ((size_t)(b * S_ + qpos)) * (KVH_ * D_) + (h >> 1) * D_ + tx * 8;
        const unsigned long long w0p = pk2(ws[row * 3],     ws[row * 3]);
        const unsigned long long w1p = pk2(ws[row * 3 + 1], ws[row * 3 + 1]);
        const unsigned long long w2p = pk2(ws[row * 3 + 2], ws[row * 3 + 2]);
#pragma unroll
        for (int dj = 0; dj < 4; dj++) {
            unsigned long long a = 0ULL;
            fma2(a, w0p, *(const unsigned long long*)(ev0 + 2 * dj));
            fma2(a, w1p, *(const unsigned long long*)(ev1 + 2 * dj));
            fma2(a, w2p, *(const unsigned long long*)(ev2 + 2 * dj));
            o2[ri][dj] = a;
        }
    }

    const float* k0b = cK + ((size_t)(b * H_ + h)) * S_ * D_;
    const float* v0b = cV + ((size_t)(b * H_ + h)) * S_ * D_;

    for (int jb = 0; jb <= qb; ++jb) {
        __syncthreads();
#pragma unroll
        for (int p = 0; p < 8; p++) {
            const int id = t + p * 256;
            const int row = id >> 5, c4 = (id & 31) * 4;
            const size_t g = ((size_t)(jb * 64 + row)) * D_ + c4;
            *(float4*)&Ks[row * 132 + c4] = *(const float4*)(k0b + g);
            *(float4*)&Vs[row * 132 + c4] = *(const float4*)(v0b + g);
        }
        __syncthreads();

        unsigned long long c2[4][4];
#pragma unroll
        for (int ri = 0; ri < 4; ri++)
#pragma unroll
            for (int rj = 0; rj < 4; rj++) c2[ri][rj] = 0ULL;

#pragma unroll 4
        for (int dt = 0; dt < 64; ++dt) {
            unsigned long long q2[4], k2[4];
#pragma unroll
            for (int ri = 0; ri < 4; ri++) q2[ri] = *(const unsigned long long*)&Qs[(ty + 16 * ri) * 132 + 2 * dt];
#pragma unroll
            for (int rj = 0; rj < 4; rj++) k2[rj] = *(const unsigned long long*)&Ks[(tx + 16 * rj) * 132 + 2 * dt];
#pragma unroll
            for (int ri = 0; ri < 4; ri++)
#pragma unroll
                for (int rj = 0; rj < 4; rj++) fma2(c2[ri][rj], q2[ri], k2[rj]);
        }

        float sv[4][4];
#pragma unroll
        for (int ri = 0; ri < 4; ri++)
#pragma unroll
            for (int rj = 0; rj < 4; rj++) {
                float2 f = upk2(c2[ri][rj]);
                sv[ri][rj] = (f.x + f.y) * scale;
            }
        if (jb == qb) {
#pragma unroll
            for (int ri = 0; ri < 4; ri++)
#pragma unroll
                for (int rj = 0; rj < 4; rj++)
                    if (tx + 16 * rj > ty + 16 * ri) sv[ri][rj] = -1e30f;
        }

#pragma unroll
        for (int ri = 0; ri < 4; ri++) {
            float mx = fmaxf(fmaxf(sv[ri][0], sv[ri][1]), fmaxf(sv[ri][2], sv[ri][3]));
#pragma unroll
            for (int off = 8; off > 0; off >>= 1) mx = fmaxf(mx, __shfl_xor_sync(0xffffffffu, mx, off));
            const float mnew = fmaxf(m_r[ri], mx);
            const float alpha = __expf(m_r[ri] - mnew);
            float rs = 0.f;
#pragma unroll
            for (int rj = 0; rj < 4; rj++) {
                const float p = __expf(sv[ri][rj] - mnew);
                Ps[(ty + 16 * ri) * 68 + tx + 16 * rj] = p;
                rs += p;
            }
#pragma unroll
            for (int off = 8; off > 0; off >>= 1) rs += __shfl_xor_sync(0xffffffffu, rs, off);
            l_r[ri] = l_r[ri] * alpha + rs;
            m_r[ri] = mnew;
            const unsigned long long ap = pk2(alpha, alpha);
#pragma unroll
            for (int dj = 0; dj < 4; dj++) mul2(o2[ri][dj], ap);
        }
        __syncthreads();

#pragma unroll 4
        for (int jj = 0; jj < 64; ++jj) {
            unsigned long long v2[4];
#pragma unroll
            for (int dj = 0; dj < 4; dj++) v2[dj] = *(const unsigned long long*)&Vs[jj * 132 + tx * 8 + 2 * dj];
#pragma unroll
            for (int ri = 0; ri < 4; ri++) {
                const float p = Ps[(ty + 16 * ri) * 68 + jj];
                const unsigned long long pp = pk2(p, p);
#pragma unroll
                for (int dj = 0; dj < 4; dj++) fma2(o2[ri][dj], pp, v2[dj]);
            }
        }
    }

#pragma unroll
    for (int ri = 0; ri < 4; ri++) {
        const int row = ty + 16 * ri;
        const int qpos = qb * 64 + row;
        const float inv = 1.f / l_r[ri];
        float* dst = g_AO + (((size_t)(b * S_ + qpos)) * H_ + h) * D_ + tx * 8;
#pragma unroll
        for (int dj = 0; dj < 4; dj++) {
            float2 f = upk2(o2[ri][dj]);
            f.x *= inv; f.y *= inv;
            *(float2*)(dst + 2 * dj) = f;
        }
    }
}

// ---------------- launch ----------------
extern "C" void kernel_launch(void* const* d_in, const int* in_sizes, int n_in,
                              void* d_out, int out_size)
{
    (void)in_sizes; (void)n_in; (void)out_size;
    const float* hidden = (const float*)d_in[0];
    const float* cosb = (const float*)d_in[2];
    const float* sinb = (const float*)d_in[3];
    const float* cK   = (const float*)d_in[4];
    const float* cV   = (const float*)d_in[5];
    const float* Wq   = (const float*)d_in[6];
    const float* Wk   = (const float*)d_in[7];
    const float* Wv   = (const float*)d_in[8];
    const float* Wo   = (const float*)d_in[9];
    float* out = (float*)d_out;

    float* pAO = nullptr;
    cudaGetSymbolAddress((void**)&pAO, g_AO);

    cudaFuncSetAttribute(attn_kernel, cudaFuncAttributeMaxDynamicSharedMemorySize, ATTN_SMEM_BYTES);

    // 1) fused QKV projection (tf32 mma.sync + ldmatrix)
    qkv_gemm<<<dim3(32, M_ / 128), 256>>>(hidden, Wq, Wk, Wv);

    // 2) RoPE on Q and K
    rope_kernel<<<(M_ * 24 * 64) / 256, 256>>>(cosb, sinb);

    // 3) flash attention (+3 diagonal extra keys)
    attn_kernel<<<dim3(32, 32), 256, ATTN_SMEM_BYTES>>>(cK, cV);

    // 4) output projection -> d_out
    gemm_nt<<<dim3(HID_ / 128, M_ / 128), 256>>>(pAO, Wo, out, HID_, HID_);
}

// round 14
// speedup vs baseline: 1.5798x; 1.5798x over previous
#include <cuda_runtime.h>
#include <cstdint>

#define B_   2
#define S_   2048
#define H_   16
#define KVH_ 8
#define D_   128
#define HID_ 2048
#define IN_  4096
#define M_   (B_*S_)

// ---------------- scratch (static device globals; no allocation) ----------------
__device__ float g_Q [(size_t)M_ * HID_];        // [tok][h*128+d]  (post-rope)
__device__ float g_K [(size_t)M_ * KVH_ * D_];   // [tok][kvh*128+d]
__device__ float g_V [(size_t)M_ * KVH_ * D_];
__device__ float g_AO[(size_t)M_ * HID_];        // attention output [b,s,h,d]

// ---------------- packed f32x2 helpers (attention) ----------------
__device__ __forceinline__ unsigned long long pk2(float lo, float hi) {
    unsigned long long r;
    asm("mov.b64 %0, {%1, %2};" : "=l"(r) : "f"(lo), "f"(hi));
    return r;
}
__device__ __forceinline__ void fma2(unsigned long long& c, unsigned long long a, unsigned long long b) {
    asm("fma.rn.f32x2 %0, %1, %2, %0;" : "+l"(c) : "l"(a), "l"(b));
}
__device__ __forceinline__ void mul2(unsigned long long& c, unsigned long long a) {
    asm("mul.rn.f32x2 %0, %0, %1;" : "+l"(c) : "l"(a));
}
__device__ __forceinline__ float2 upk2(unsigned long long v) {
    float2 f;
    asm("mov.b64 {%0, %1}, %2;" : "=f"(f.x), "=f"(f.y) : "l"(v));
    return f;
}

// ---------------- tf32 / ldmatrix helpers ----------------
__device__ __forceinline__ uint32_t f2tf(float x) {
    uint32_t r;
    asm("cvt.rna.tf32.f32 %0, %1;" : "=r"(r) : "f"(x));
    return r;
}
__device__ __forceinline__ uint32_t smem_u32(const void* p) {
    uint32_t a;
    asm("{ .reg .u64 t; cvta.to.shared.u64 t, %1; cvt.u32.u64 %0, t; }" : "=r"(a) : "l"(p));
    return a;
}
__device__ __forceinline__ void mma_tf32(float* d, const uint32_t* a, const uint32_t* b) {
    asm volatile("mma.sync.aligned.m16n8k8.row.col.f32.tf32.tf32.f32 "
        "{%0,%1,%2,%3}, {%4,%5,%6,%7}, {%8,%9}, {%0,%1,%2,%3};"
        : "+f"(d[0]), "+f"(d[1]), "+f"(d[2]), "+f"(d[3])
        : "r"(a[0]), "r"(a[1]), "r"(a[2]), "r"(a[3]), "r"(b[0]), "r"(b[1]));
}
__device__ __forceinline__ void ldsm_x4(uint32_t* r, uint32_t addr) {
    asm volatile("ldmatrix.sync.aligned.m8n8.x4.shared.b16 {%0,%1,%2,%3}, [%4];"
        : "=r"(r[0]), "=r"(r[1]), "=r"(r[2]), "=r"(r[3]) : "r"(addr));
}
__device__ __forceinline__ void ldsm_x2(uint32_t* r, uint32_t addr) {
    asm volatile("ldmatrix.sync.aligned.m8n8.x2.shared.b16 {%0,%1}, [%2];"
        : "=r"(r[0]), "=r"(r[1]) : "r"(addr));
}

// ---------------- tf32 tensor-core GEMM:  C[m][n] = sum_k A[m][k]*W[n][k] ----------------
// 128x128 block tile, BK=16, 256 threads (8 warps as 2m x 4n -> warp tile 64x32),
// mma.m16n8k8. Fragments loaded with ldmatrix: A = LDSM.x4 (one per m16k8 frag),
// B = LDSM.x2 (one per n8k8 frag). Smem row-major with pad 20 (80B row stride ->
// 8 ldmatrix row-pointers hit 8 distinct banks). Single buffer + register prefetch.
__device__ __forceinline__ void gemm_tf32_body(const float* __restrict__ A,
                                               const float* __restrict__ W,
                                               float* __restrict__ C,
                                               int Ndim, int Kdim, int m0, int n0)
{
    __shared__ uint32_t As[128][20];
    __shared__ uint32_t Ws[128][20];

    const int t    = threadIdx.x;
    const int warp = t >> 5, lane = t & 31;
    const int grp  = lane >> 2, tig = lane & 3;
    const int wm   = (warp >> 2) * 64;   // 0 / 64
    const int wn   = (warp & 3) * 32;    // 0..96

    // ldmatrix per-lane row pointers
    const int l8 = lane & 7, lq = lane >> 3;     // lq = matrix index 0..3
    const uint32_t sA = smem_u32(As);
    const uint32_t sW = smem_u32(Ws);
    // A frag (m16k8): block j: rows +8*(j&1), cols +4*(j>>1)
    const uint32_t aBase = sA + (uint32_t)(((wm + (lq & 1) * 8 + l8) * 20 + (lq >> 1) * 4) << 2);
    // B frag (n8k8): block j (x2 uses lanes 0-15): cols +4*(j&1)
    const uint32_t bBase = sW + (uint32_t)(((wn + l8) * 20 + (lq & 1) * 4) << 2);

    // loaders: 128 rows x 16 k = 512 float4 each; 2 rows per thread
    const int rowX = t >> 2;             // 0..63
    const int kc   = (t & 3) * 4;        // 0,4,8,12

    const float* Ap0 = A + (size_t)(m0 + rowX) * Kdim + kc;
    const float* Ap1 = A + (size_t)(m0 + rowX + 64) * Kdim + kc;
    const float* Wp0 = W + (size_t)(n0 + rowX) * Kdim + kc;
    const float* Wp1 = W + (size_t)(n0 + rowX + 64) * Kdim + kc;

    float acc[4][4][4];
#pragma unroll
    for (int i = 0; i < 4; i++)
#pragma unroll
        for (int j = 0; j < 4; j++)
#pragma unroll
            for (int r = 0; r < 4; r++) acc[i][j][r] = 0.f;

    float4 fa0 = *(const float4*)Ap0;
    float4 fa1 = *(const float4*)Ap1;
    float4 fb0 = *(const float4*)Wp0;
    float4 fb1 = *(const float4*)Wp1;

    const int KT = Kdim >> 4;
    for (int kt = 0; kt < KT; ++kt) {
        // stage current tile (rna->tf32), vectorized STS.128
        *(uint4*)&As[rowX][kc]       = make_uint4(f2tf(fa0.x), f2tf(fa0.y), f2tf(fa0.z), f2tf(fa0.w));
        *(uint4*)&As[rowX + 64][kc]  = make_uint4(f2tf(fa1.x), f2tf(fa1.y), f2tf(fa1.z), f2tf(fa1.w));
        *(uint4*)&Ws[rowX][kc]       = make_uint4(f2tf(fb0.x), f2tf(fb0.y), f2tf(fb0.z), f2tf(fb0.w));
        *(uint4*)&Ws[rowX + 64][kc]  = make_uint4(f2tf(fb1.x), f2tf(fb1.y), f2tf(fb1.z), f2tf(fb1.w));
        __syncthreads();

        // prefetch next k-tile into registers
        if (kt + 1 < KT) {
            const int off = (kt + 1) << 4;
            fa0 = *(const float4*)(Ap0 + off);
            fa1 = *(const float4*)(Ap1 + off);
            fb0 = *(const float4*)(Wp0 + off);
            fb1 = *(const float4*)(Wp1 + off);
        }

#pragma unroll
        for (int ks = 0; ks < 16; ks += 8) {
            uint32_t a[4][4], b[4][2];
#pragma unroll
            for (int mt = 0; mt < 4; mt++)
                ldsm_x4(a[mt], aBase + (uint32_t)((mt * 16 * 20 + ks) << 2));
#pragma unroll
            for (int nt = 0; nt < 4; nt++)
                ldsm_x2(b[nt], bBase + (uint32_t)((nt * 8 * 20 + ks) << 2));
#pragma unroll
            for (int mt = 0; mt < 4; mt++)
#pragma unroll
                for (int nt = 0; nt < 4; nt++)
                    mma_tf32(acc[mt][nt], a[mt], b[nt]);
        }
        __syncthreads();
    }

    // epilogue: c0,c1 -> (row, col..col+1); c2,c3 -> (row+8, ...)
#pragma unroll
    for (int mt = 0; mt < 4; mt++) {
        const int row = m0 + wm + mt * 16 + grp;
#pragma unroll
        for (int nt = 0; nt < 4; nt++) {
            const int col = n0 + wn + nt * 8 + tig * 2;
            *(float2*)(C + (size_t)row * Ndim + col)       = make_float2(acc[mt][nt][0], acc[mt][nt][1]);
            *(float2*)(C + (size_t)(row + 8) * Ndim + col) = make_float2(acc[mt][nt][2], acc[mt][nt][3]);
        }
    }
}

// fused QKV GEMM: n-blocks of 128 cover Wq (16), Wk (8), Wv (8)
__global__ __launch_bounds__(256, 2)
void qkv_gemm(const float* __restrict__ A,
              const float* __restrict__ Wq,
              const float* __restrict__ Wk,
              const float* __restrict__ Wv)
{
    const int nb = blockIdx.x;
    const int m0 = blockIdx.y << 7;
    const float* W;
    float* C;
    int Ndim, n0;
    if (nb < 16)      { W = Wq; C = g_Q; Ndim = HID_;       n0 = nb * 128; }
    else if (nb < 24) { W = Wk; C = g_K; Ndim = KVH_ * D_;  n0 = (nb - 16) * 128; }
    else              { W = Wv; C = g_V; Ndim = KVH_ * D_;  n0 = (nb - 24) * 128; }
    gemm_tf32_body(A, W, C, Ndim, IN_, m0, n0);
}

__global__ __launch_bounds__(256, 2)
void gemm_nt(const float* __restrict__ A, const float* __restrict__ W,
             float* __restrict__ C, int Ndim, int Kdim)
{
    gemm_tf32_body(A, W, C, Ndim, Kdim, blockIdx.y << 7, blockIdx.x << 7);
}

// ---------------- RoPE (in-place on g_Q, g_K) ----------------
__global__ void rope_kernel(const float* __restrict__ cosb, const float* __restrict__ sinb)
{
    const int idx  = blockIdx.x * 256 + threadIdx.x;
    const int d    = idx & 63;
    const int rest = idx >> 6;
    const int head = rest % 24;       // 0..15 -> Q heads, 16..23 -> K heads
    const int tok  = rest / 24;
    const float c1 = cosb[(size_t)tok * D_ + d];
    const float s1 = sinb[(size_t)tok * D_ + d];
    const float c2 = cosb[(size_t)tok * D_ + d + 64];
    const float s2 = sinb[(size_t)tok * D_ + d + 64];
    float* X = (head < 16) ? (g_Q + (size_t)tok * HID_ + head * D_)
                           : (g_K + (size_t)tok * (KVH_ * D_) + (head - 16) * D_);
    const float x1 = X[d], x2 = X[d + 64];
    X[d]      = x1 * c1 - x2 * s1;
    X[d + 64] = x2 * c2 + x1 * s2;
}

// ---------------- flash attention (fp32 FFMA2, unchanged) ----------------
#define QS_OFF 0
#define KS_OFF (64*132)
#define VS_OFF (2*64*132)
#define PS_OFF (3*64*132)
#define ES_OFF (PS_OFF + 64*68)
#define WS_OFF (ES_OFF + 192)
#define MS_OFF (WS_OFF + 192)
#define LS_OFF (MS_OFF + 64)
#define ATTN_SMEM_FLOATS (LS_OFF + 64)
#define ATTN_SMEM_BYTES  (ATTN_SMEM_FLOATS * 4)

__global__ __launch_bounds__(256)
void attn_kernel(const float* __restrict__ cK, const float* __restrict__ cV)
{
    extern __shared__ float sm[];
    float* Qs   = sm + QS_OFF;
    float* Ks   = sm + KS_OFF;
    float* Vs   = sm + VS_OFF;
    float* Ps   = sm + PS_OFF;
    float* es   = sm + ES_OFF;
    float* ws   = sm + WS_OFF;
    float* ms_s = sm + MS_OFF;
    float* ls_s = sm + LS_OFF;

    const int t  = threadIdx.x, tx = t & 15, ty = t >> 4;
    const int bh = blockIdx.x;
    const int qb = (int)gridDim.y - 1 - (int)blockIdx.y;
    const int b  = bh >> 4, h = bh & 15;
    const float scale = 0.08838834764831845f;

    const size_t q_row0 = ((size_t)(b * S_) + qb * 64) * HID_ + h * D_;
#pragma unroll
    for (int p = 0; p < 8; p++) {
        const int id = t + p * 256;
        const int row = id >> 5, c4 = (id & 31) * 4;
        *(float4*)&Qs[row * 132 + c4] = *(const float4*)(g_Q + q_row0 + (size_t)row * HID_ + c4);
    }
    __syncthreads();

    if (t < 192) {
        const int row = t & 63, l = t >> 6;
        const int qpos = qb * 64 + row;
        const float* ek;
        if (l == 2) ek = g_K + ((size_t)(b * S_ + qpos)) * (KVH_ * D_) + (h >> 1) * D_;
        else        ek = cK + (((size_t)((l + 1) * B_ + b) * H_ + h) * S_ + qpos) * D_;
        float acc = 0.f;
#pragma unroll 8
        for (int dd = 0; dd < 128; dd += 4) {
            float4 kv = *(const float4*)(ek + dd);
            float4 qv = *(const float4*)&Qs[row * 132 + dd];
            acc += qv.x * kv.x + qv.y * kv.y + qv.z * kv.z + qv.w * kv.w;
        }
        es[row * 3 + l] = acc * scale;
    }
    __syncthreads();
    if (t < 64) {
        const float e0 = es[t * 3], e1 = es[t * 3 + 1], e2 = es[t * 3 + 2];
        const float mm = fmaxf(e0, fmaxf(e1, e2));
        const float w0 = __expf(e0 - mm), w1 = __expf(e1 - mm), w2 = __expf(e2 - mm);
        ws[t * 3] = w0; ws[t * 3 + 1] = w1; ws[t * 3 + 2] = w2;
        ms_s[t] = mm; ls_s[t] = w0 + w1 + w2;
    }
    __syncthreads();

    float m_r[4], l_r[4];
    unsigned long long o2[4][4];
#pragma unroll
    for (int ri = 0; ri < 4; ri++) {
        const int row = ty + 16 * ri;
        const int qpos = qb * 64 + row;
        m_r[ri] = ms_s[row]; l_r[ri] = ls_s[row];
        const float* ev0 = cV + (((size_t)(1 * B_ + b) * H_ + h) * S_ + qpos) * D_ + tx * 8;
        const float* ev1 = cV + (((size_t)(2 * B_ + b) * H_ + h) * S_ + qpos) * D_ + tx * 8;
        const float* ev2 = g_V + ((size_t)(b * S_ + qpos)) * (KVH_ * D_) + (h >> 1) * D_ + tx * 8;
        const unsigned long long w0p = pk2(ws[row * 3],     ws[row * 3]);
        const unsigned long long w1p = pk2(ws[row * 3 + 1], ws[row * 3 + 1]);
        const unsigned long long w2p = pk2(ws[row * 3 + 2], ws[row * 3 + 2]);
#pragma unroll
        for (int dj = 0; dj < 4; dj++) {
            unsigned long long a = 0ULL;
            fma2(a, w0p, *(const unsigned long long*)(ev0 + 2 * dj));
            fma2(a, w1p, *(const unsigned long long*)(ev1 + 2 * dj));
            fma2(a, w2p, *(const unsigned long long*)(ev2 + 2 * dj));
            o2[ri][dj] = a;
        }
    }

    const float* k0b = cK + ((size_t)(b * H_ + h)) * S_ * D_;
    const float* v0b = cV + ((size_t)(b * H_ + h)) * S_ * D_;

    for (int jb = 0; jb <= qb; ++jb) {
        __syncthreads();
#pragma unroll
        for (int p = 0; p < 8; p++) {
            const int id = t + p * 256;
            const int row = id >> 5, c4 = (id & 31) * 4;
            const size_t g = ((size_t)(jb * 64 + row)) * D_ + c4;
            *(float4*)&Ks[row * 132 + c4] = *(const float4*)(k0b + g);
            *(float4*)&Vs[row * 132 + c4] = *(const float4*)(v0b + g);
        }
        __syncthreads();

        unsigned long long c2[4][4];
#pragma unroll
        for (int ri = 0; ri < 4; ri++)
#pragma unroll
            for (int rj = 0; rj < 4; rj++) c2[ri][rj] = 0ULL;

#pragma unroll 4
        for (int dt = 0; dt < 64; ++dt) {
            unsigned long long q2[4], k2[4];
#pragma unroll
            for (int ri = 0; ri < 4; ri++) q2[ri] = *(const unsigned long long*)&Qs[(ty + 16 * ri) * 132 + 2 * dt];
#pragma unroll
            for (int rj = 0; rj < 4; rj++) k2[rj] = *(const unsigned long long*)&Ks[(tx + 16 * rj) * 132 + 2 * dt];
#pragma unroll
            for (int ri = 0; ri < 4; ri++)
#pragma unroll
                for (int rj = 0; rj < 4; rj++) fma2(c2[ri][rj], q2[ri], k2[rj]);
        }

        float sv[4][4];
#pragma unroll
        for (int ri = 0; ri < 4; ri++)
#pragma unroll
            for (int rj = 0; rj < 4; rj++) {
                float2 f = upk2(c2[ri][rj]);
                sv[ri][rj] = (f.x + f.y) * scale;
            }
        if (jb == qb) {
#pragma unroll
            for (int ri = 0; ri < 4; ri++)
#pragma unroll
                for (int rj = 0; rj < 4; rj++)
                    if (tx + 16 * rj > ty + 16 * ri) sv[ri][rj] = -1e30f;
        }

#pragma unroll
        for (int ri = 0; ri < 4; ri++) {
            float mx = fmaxf(fmaxf(sv[ri][0], sv[ri][1]), fmaxf(sv[ri][2], sv[ri][3]));
#pragma unroll
            for (int off = 8; off > 0; off >>= 1) mx = fmaxf(mx, __shfl_xor_sync(0xffffffffu, mx, off));
            const float mnew = fmaxf(m_r[ri], mx);
            const float alpha = __expf(m_r[ri] - mnew);
            float rs = 0.f;
#pragma unroll
            for (int rj = 0; rj < 4; rj++) {
                const float p = __expf(sv[ri][rj] - mnew);
                Ps[(ty + 16 * ri) * 68 + tx + 16 * rj] = p;
                rs += p;
            }
#pragma unroll
            for (int off = 8; off > 0; off >>= 1) rs += __shfl_xor_sync(0xffffffffu, rs, off);
            l_r[ri] = l_r[ri] * alpha + rs;
            m_r[ri] = mnew;
            const unsigned long long ap = pk2(alpha, alpha);
#pragma unroll
            for (int dj = 0; dj < 4; dj++) mul2(o2[ri][dj], ap);
        }
        __syncthreads();

#pragma unroll 4
        for (int jj = 0; jj < 64; ++jj) {
            unsigned long long v2[4];
#pragma unroll
            for (int dj = 0; dj < 4; dj++) v2[dj] = *(const unsigned long long*)&Vs[jj * 132 + tx * 8 + 2 * dj];
#pragma unroll
            for (int ri = 0; ri < 4; ri++) {
                const float p = Ps[(ty + 16 * ri) * 68 + jj];
                const unsigned long long pp = pk2(p, p);
#pragma unroll
                for (int dj = 0; dj < 4; dj++) fma2(o2[ri][dj], pp, v2[dj]);
            }
        }
    }

#pragma unroll
    for (int ri = 0; ri < 4; ri++) {
        const int row = ty + 16 * ri;
        const int qpos = qb * 64 + row;
        const float inv = 1.f / l_r[ri];
        float* dst = g_AO + (((size_t)(b * S_ + qpos)) * H_ + h) * D_ + tx * 8;
#pragma unroll
        for (int dj = 0; dj < 4; dj++) {
            float2 f = upk2(o2[ri][dj]);
            f.x *= inv; f.y *= inv;
            *(float2*)(dst + 2 * dj) = f;
        }
    }
}

// ---------------- launch ----------------
extern "C" void kernel_launch(void* const* d_in, const int* in_sizes, int n_in,
                              void* d_out, int out_size)
{
    (void)in_sizes; (void)n_in; (void)out_size;
    const float* hidden = (const float*)d_in[0];
    const float* cosb = (const float*)d_in[2];
    const float* sinb = (const float*)d_in[3];
    const float* cK   = (const float*)d_in[4];
    const float* cV   = (const float*)d_in[5];
    const float* Wq   = (const float*)d_in[6];
    const float* Wk   = (const float*)d_in[7];
    const float* Wv   = (const float*)d_in[8];
    const float* Wo   = (const float*)d_in[9];
    float* out = (float*)d_out;

    float* pAO = nullptr;
    cudaGetSymbolAddress((void**)&pAO, g_AO);

    cudaFuncSetAttribute(attn_kernel, cudaFuncAttributeMaxDynamicSharedMemorySize, ATTN_SMEM_BYTES);

    // 1) fused QKV projection (tf32 mma.sync + ldmatrix)
    qkv_gemm<<<dim3(32, M_ / 128), 256>>>(hidden, Wq, Wk, Wv);

    // 2) RoPE on Q and K
    rope_kernel<<<(M_ * 24 * 64) / 256, 256>>>(cosb, sinb);

    // 3) flash attention (+3 diagonal extra keys)
    attn_kernel<<<dim3(32, 32), 256, ATTN_SMEM_BYTES>>>(cK, cV);

    // 4) output projection -> d_out
    gemm_nt<<<dim3(HID_ / 128, M_ / 128), 256>>>(pAO, Wo, out, HID_, HID_);
}